// round 13
// baseline (speedup 1.0000x reference)
#include <cuda_runtime.h>
#include <stdint.h>

#define N_NODES 100000
#define D_IN    128
#define D_H     64
#define D_OUT   32
#define CAP     64          // max in-degree slots (multinomial mean 16, max ~35)
#define G1_BLOCKS ((N_NODES + 63) / 64)      // 1563
#define EPB     1024        // edges per phase1 block (1563*1024 >= 1.6M)

// ---------------- scratch (static device globals; no allocation) ----------------
__device__ int   g_wp  [N_NODES];                        // fill cursor == in-degree
__device__ float g_dinv[N_NODES];
__device__ __align__(16) int   g_col[N_NODES * CAP];     // src lists per dst
__device__ __align__(16) float g_g1 [N_NODES * D_H];     // x@W1 (UNscaled)
__device__ __align__(16) float g_h1d[N_NODES * D_H];     // relu+dropout result
__device__ __align__(16) float g_g2 [N_NODES * D_OUT];   // (h1d@W2) * dinv[n]

__device__ __forceinline__ float4 f4add(float4 a, float4 b) {
    return make_float4(a.x + b.x, a.y + b.y, a.z + b.z, a.w + b.w);
}
__device__ __forceinline__ float4 f4fma(float4 v, float s, float4 a) {
    return make_float4(fmaf(v.x, s, a.x), fmaf(v.y, s, a.y),
                       fmaf(v.z, s, a.z), fmaf(v.w, s, a.w));
}

// Exact JAX threefry2x32 (20 rounds), key = (k0, k1)
__device__ __forceinline__ void threefry2x32(uint32_t k0, uint32_t k1,
                                             uint32_t x0, uint32_t x1,
                                             uint32_t& o0, uint32_t& o1) {
    uint32_t ks2 = k0 ^ k1 ^ 0x1BD11BDAu;
    x0 += k0; x1 += k1;
#define TFR(r) { x0 += x1; x1 = (x1 << r) | (x1 >> (32 - r)); x1 ^= x0; }
    TFR(13) TFR(15) TFR(26) TFR(6)
    x0 += k1;  x1 += ks2 + 1u;
    TFR(17) TFR(29) TFR(16) TFR(24)
    x0 += ks2; x1 += k0 + 2u;
    TFR(13) TFR(15) TFR(26) TFR(6)
    x0 += k0;  x1 += k1 + 3u;
    TFR(17) TFR(29) TFR(16) TFR(24)
    x0 += k1;  x1 += ks2 + 4u;
    TFR(13) TFR(15) TFR(26) TFR(6)
    x0 += ks2; x1 += k0 + 5u;
#undef TFR
    o0 = x0; o1 = x1;
}

// ---------------- kernels ----------------
__global__ void zero_kernel() {
    int i = blockIdx.x * blockDim.x + threadIdx.x;
    if (i < N_NODES) g_wp[i] = 0;
}

// Phase 1: CSR fill (prologue, atomic/LTS-bound) overlapped with
// gemm1 g1[n,:] = x[n,:] @ W1 (UNscaled; FMA-bound).
// 64 nodes/block, 128 threads, thread tile 8m x 4j.
__global__ __launch_bounds__(128) void phase1_kernel(const float* __restrict__ x,
                                                     const float* __restrict__ W1,
                                                     const int* __restrict__ ei, int E) {
    __shared__ float sW[D_IN * D_H];          // 32 KB, [k][j]
    __shared__ float sA[64 * D_IN];           // 32 KB, [m][k]
    int tid = threadIdx.x;                    // 0..127
    int n0  = blockIdx.x * 64;

    // stage smem loads first (long-latency LDGs overlap the fill atomics)
    const float4* Wv = (const float4*)W1;
    float4* sWv = (float4*)sW;
    #pragma unroll
    for (int i = 0; i < 16; i++) sWv[tid + 128 * i] = Wv[tid + 128 * i];

    const float4* xv = (const float4*)x;
    float4* sAv = (float4*)sA;
    #pragma unroll
    for (int i = 0; i < 16; i++) {
        int v = tid + 128 * i;                // 0..2047
        int r = v >> 5, c = v & 31;
        int n = n0 + r;
        sAv[v] = (n < N_NODES) ? xv[(size_t)n * 32 + c]
                               : make_float4(0.f, 0.f, 0.f, 0.f);
    }

    // fill prologue: this block's 1024-edge slice, 8 independent atomics/thread
    {
        int e0 = blockIdx.x * EPB + tid;
        #pragma unroll
        for (int i = 0; i < EPB / 128; i++) {
            int e = e0 + i * 128;
            if (e < E) {
                int d = ei[E + e];
                int s = ei[e];
                int p = atomicAdd(&g_wp[d], 1);
                if (p < CAP) g_col[d * CAP + p] = s;
            }
        }
    }
    __syncthreads();

    int tx = tid & 15;                        // j = tx + 16*jj
    int mg = tid >> 4;                        // 0..7 -> rows mg*8..mg*8+7
    float acc[8][4] = {};

    #pragma unroll 2
    for (int k4 = 0; k4 < D_IN / 4; k4++) {
        float4 a[8];
        #pragma unroll
        for (int m = 0; m < 8; m++)
            a[m] = ((const float4*)&sA[(mg * 8 + m) * D_IN])[k4];
        #pragma unroll
        for (int kk = 0; kk < 4; kk++) {
            int k = k4 * 4 + kk;
            float w[4];
            #pragma unroll
            for (int jj = 0; jj < 4; jj++) w[jj] = sW[k * D_H + tx + 16 * jj];
            #pragma unroll
            for (int m = 0; m < 8; m++) {
                float av = ((const float*)&a[m])[kk];
                #pragma unroll
                for (int jj = 0; jj < 4; jj++) acc[m][jj] += av * w[jj];
            }
        }
    }

    #pragma unroll
    for (int m = 0; m < 8; m++) {
        int n = n0 + mg * 8 + m;
        if (n < N_NODES) {
            #pragma unroll
            for (int jj = 0; jj < 4; jj++)
                g_g1[(size_t)n * D_H + tx + 16 * jj] = acc[m][jj];   // unscaled
        }
    }
}

__global__ void dinv_kernel() {
    int i = blockIdx.x * blockDim.x + threadIdx.x;
    if (i < N_NODES) g_dinv[i] = rsqrtf((float)(g_wp[i] + 1));  // +1 self-loop
}

// ---------------- Gather 1 + relu + dropout (fused) ----------------
// 16 lanes per node; lane owns one float4 column of the 64-float row.
// acc = g1raw[n]*dinv[n] + sum_s g1raw[s]*dinv[s]; out = acc*dinv[n]+b1.
__global__ __launch_bounds__(256) void gather1_kernel(const float* __restrict__ b1) {
    int tid  = threadIdx.x;
    int lane = tid & 15;
    int node = blockIdx.x * 16 + (tid >> 4);

    const float4* g1v = (const float4*)g_g1;
    float di = g_dinv[node];
    size_t rl = (size_t)node * 16 + lane;

    float4 acc0 = make_float4(0.f, 0.f, 0.f, 0.f);
    float4 acc1 = make_float4(0.f, 0.f, 0.f, 0.f);
    {
        float4 sv = g1v[rl];                 // self-loop term * dinv[n]
        acc0 = f4fma(sv, di, acc0);
    }

    int deg = g_wp[node];
    const int* cp = g_col + node * CAP;

    int j = 0;
    for (; j + 4 <= deg; j += 4) {
        int4 s4 = *(const int4*)(cp + j);
        float d0 = g_dinv[s4.x], d1 = g_dinv[s4.y];
        float d2 = g_dinv[s4.z], d3 = g_dinv[s4.w];
        float4 v0 = g1v[(size_t)s4.x * 16 + lane];
        float4 v1 = g1v[(size_t)s4.y * 16 + lane];
        float4 v2 = g1v[(size_t)s4.z * 16 + lane];
        float4 v3 = g1v[(size_t)s4.w * 16 + lane];
        acc0 = f4fma(v0, d0, acc0);
        acc1 = f4fma(v1, d1, acc1);
        acc0 = f4fma(v2, d2, acc0);
        acc1 = f4fma(v3, d3, acc1);
    }
    for (; j < deg; j++) {
        int s = cp[j];
        acc0 = f4fma(g1v[(size_t)s * 16 + lane], g_dinv[s], acc0);
    }
    float4 acc = f4add(acc0, acc1);

    float4 bb = ((const float4*)b1)[lane];
    float v[4] = { fmaxf(acc.x * di + bb.x, 0.f),
                   fmaxf(acc.y * di + bb.y, 0.f),
                   fmaxf(acc.z * di + bb.z, 0.f),
                   fmaxf(acc.w * di + bb.w, 0.f) };

    // Partitionable threefry: bits = o0 ^ o1 of threefry(key, 0, elem_idx)
    uint32_t gidx = (uint32_t)(node * D_H + lane * 4);
    float4 outv;
    #pragma unroll
    for (int k = 0; k < 4; k++) {
        uint32_t o0, o1;
        threefry2x32(0u, 42u, 0u, gidx + k, o0, o1);
        uint32_t bits = o0 ^ o1;
        float u = __uint_as_float((bits >> 9) | 0x3f800000u) - 1.0f;
        ((float*)&outv)[k] = (u < 0.8f) ? v[k] * 1.25f : 0.f;
    }
    ((float4*)g_h1d)[rl] = outv;
}

// ---------------- GEMM 2: g2[n,:] = (h1d[n,:] @ W2) * dinv[n] ----------------
// 64 nodes/block, 256 threads. Thread tile 4m x 2j, k vectorized by 4.
__global__ __launch_bounds__(256) void gemm2_kernel(const float* __restrict__ W2) {
    __shared__ float sW[D_H * D_OUT];         // 8 KB, [k][j]
    __shared__ float sA[64 * D_H];            // 16 KB, [m][k]
    int tid = threadIdx.x;
    int n0  = blockIdx.x * 64;

    #pragma unroll
    for (int i = 0; i < 2; i++)
        ((float4*)sW)[tid + 256 * i] = ((const float4*)W2)[tid + 256 * i];

    const float4* hv = (const float4*)g_h1d;
    float4* sAv = (float4*)sA;
    #pragma unroll
    for (int i = 0; i < 4; i++) {
        int v = tid + 256 * i;
        int r = v >> 4, c = v & 15;
        int n = n0 + r;
        sAv[v] = (n < N_NODES) ? hv[(size_t)n * 16 + c]
                               : make_float4(0.f, 0.f, 0.f, 0.f);
    }
    __syncthreads();

    int tx = tid & 15;
    int mg = tid >> 4;
    float acc[4][2] = {};

    #pragma unroll 4
    for (int k4 = 0; k4 < D_H / 4; k4++) {
        float4 a[4];
        #pragma unroll
        for (int m = 0; m < 4; m++)
            a[m] = ((const float4*)&sA[(mg * 4 + m) * D_H])[k4];
        #pragma unroll
        for (int kk = 0; kk < 4; kk++) {
            int k = k4 * 4 + kk;
            float w0 = sW[k * D_OUT + tx];
            float w1 = sW[k * D_OUT + tx + 16];
            #pragma unroll
            for (int m = 0; m < 4; m++) {
                float av = ((const float*)&a[m])[kk];
                acc[m][0] += av * w0;
                acc[m][1] += av * w1;
            }
        }
    }

    #pragma unroll
    for (int m = 0; m < 4; m++) {
        int n = n0 + mg * 4 + m;
        if (n < N_NODES) {
            float di = g_dinv[n];
            g_g2[(size_t)n * D_OUT + tx]      = acc[m][0] * di;
            g_g2[(size_t)n * D_OUT + tx + 16] = acc[m][1] * di;
        }
    }
}

// ---------------- Gather 2 + bias (fused final) ----------------
// 8 lanes per node; lane owns one float4 of the 32-float row.
__global__ __launch_bounds__(256) void gather2_kernel(const float* __restrict__ b2,
                                                      float* __restrict__ out) {
    int tid  = threadIdx.x;
    int lane = tid & 7;
    int node = blockIdx.x * 32 + (tid >> 3);

    const float4* g2v = (const float4*)g_g2;
    size_t rl = (size_t)node * 8 + lane;
    float4 acc0 = g2v[rl];                       // self-loop
    float4 acc1 = make_float4(0.f, 0.f, 0.f, 0.f);

    int deg = g_wp[node];
    const int* cp = g_col + node * CAP;

    int j = 0;
    for (; j + 4 <= deg; j += 4) {
        int4 s4 = *(const int4*)(cp + j);
        float4 v0 = g2v[(size_t)s4.x * 8 + lane];
        float4 v1 = g2v[(size_t)s4.y * 8 + lane];
        float4 v2 = g2v[(size_t)s4.z * 8 + lane];
        float4 v3 = g2v[(size_t)s4.w * 8 + lane];
        acc0 = f4add(acc0, f4add(v0, v1));
        acc1 = f4add(acc1, f4add(v2, v3));
    }
    for (; j < deg; j++) {
        int s = cp[j];
        acc0 = f4add(acc0, g2v[(size_t)s * 8 + lane]);
    }
    float4 acc = f4add(acc0, acc1);

    float di = g_dinv[node];
    float4 bb = ((const float4*)b2)[lane];
    float4 o = make_float4(acc.x * di + bb.x, acc.y * di + bb.y,
                           acc.z * di + bb.z, acc.w * di + bb.w);
    ((float4*)out)[rl] = o;
}

// ---------------- launch ----------------
extern "C" void kernel_launch(void* const* d_in, const int* in_sizes, int n_in,
                              void* d_out, int out_size) {
    const float* x  = (const float*)d_in[0];
    const int*   ei = (const int*)d_in[1];     // int32 (JAX x64 disabled)
    const float* W1 = (const float*)d_in[2];
    const float* b1 = (const float*)d_in[3];
    const float* W2 = (const float*)d_in[4];
    const float* b2 = (const float*)d_in[5];
    float* out = (float*)d_out;
    const int E = in_sizes[1] / 2;

    const int T = 256;
    zero_kernel<<<(N_NODES + T - 1) / T, T>>>();
    phase1_kernel<<<G1_BLOCKS, 128>>>(x, W1, ei, E);
    dinv_kernel<<<(N_NODES + T - 1) / T, T>>>();
    gather1_kernel<<<(N_NODES + 15) / 16, T>>>(b1);
    gemm2_kernel<<<(N_NODES + 63) / 64, T>>>(W2);
    gather2_kernel<<<(N_NODES + 31) / 32, T>>>(b2, out);
}

// round 15
// speedup vs baseline: 1.1320x; 1.1320x over previous
#include <cuda_runtime.h>
#include <stdint.h>

#define N_NODES 100000
#define D_IN    128
#define D_H     64
#define D_OUT   32
#define CAP     64          // max in-degree slots (multinomial mean 16, max ~35)

// ---------------- scratch (static device globals; no allocation) ----------------
__device__ int   g_wp  [N_NODES];                        // fill cursor == in-degree
__device__ float g_dinv[N_NODES];
__device__ __align__(16) int   g_col[N_NODES * CAP];     // src lists per dst
__device__ __align__(16) float g_g1 [N_NODES * D_H];     // x@W1, then scaled in-place
__device__ __align__(16) float g_h1d[N_NODES * D_H];     // relu+dropout result
__device__ __align__(16) float g_g2 [N_NODES * D_OUT];   // (h1d@W2) * dinv[n]

__device__ __forceinline__ float4 f4add(float4 a, float4 b) {
    return make_float4(a.x + b.x, a.y + b.y, a.z + b.z, a.w + b.w);
}

// Exact JAX threefry2x32 (20 rounds), key = (k0, k1)
__device__ __forceinline__ void threefry2x32(uint32_t k0, uint32_t k1,
                                             uint32_t x0, uint32_t x1,
                                             uint32_t& o0, uint32_t& o1) {
    uint32_t ks2 = k0 ^ k1 ^ 0x1BD11BDAu;
    x0 += k0; x1 += k1;
#define TFR(r) { x0 += x1; x1 = (x1 << r) | (x1 >> (32 - r)); x1 ^= x0; }
    TFR(13) TFR(15) TFR(26) TFR(6)
    x0 += k1;  x1 += ks2 + 1u;
    TFR(17) TFR(29) TFR(16) TFR(24)
    x0 += ks2; x1 += k0 + 2u;
    TFR(13) TFR(15) TFR(26) TFR(6)
    x0 += k0;  x1 += k1 + 3u;
    TFR(17) TFR(29) TFR(16) TFR(24)
    x0 += k1;  x1 += ks2 + 4u;
    TFR(13) TFR(15) TFR(26) TFR(6)
    x0 += ks2; x1 += k0 + 5u;
#undef TFR
    o0 = x0; o1 = x1;
}

// ---------------- CSR-lite build (side stream) ----------------
__global__ void zero_kernel() {
    int i = blockIdx.x * blockDim.x + threadIdx.x;
    if (i < N_NODES) g_wp[i] = 0;
}

// single atomic per edge: cursor doubles as histogram
__global__ void fill_kernel(const int* __restrict__ ei, int E) {
    int e = blockIdx.x * blockDim.x + threadIdx.x;
    if (e >= E) return;
    int d = ei[E + e];
    int p = atomicAdd(&g_wp[d], 1);
    if (p < CAP) g_col[d * CAP + p] = ei[e];
}

__global__ void dinv_kernel() {
    int i = blockIdx.x * blockDim.x + threadIdx.x;
    if (i < N_NODES) g_dinv[i] = rsqrtf((float)(g_wp[i] + 1));  // +1 self-loop
}

// ---------------- GEMM 1 (main stream, concurrent with CSR build) ----------------
// g1[n,:] = x[n,:] @ W1  (UNscaled). 64 nodes/block, 128 threads, tile 8m x 4j.
__global__ __launch_bounds__(128) void gemm1_kernel(const float* __restrict__ x,
                                                    const float* __restrict__ W1) {
    __shared__ float sW[D_IN * D_H];          // 32 KB, [k][j]
    __shared__ float sA[64 * D_IN];           // 32 KB, [m][k]
    int tid = threadIdx.x;                    // 0..127
    int n0  = blockIdx.x * 64;

    const float4* Wv = (const float4*)W1;
    float4* sWv = (float4*)sW;
    #pragma unroll
    for (int i = 0; i < 16; i++) sWv[tid + 128 * i] = Wv[tid + 128 * i];

    const float4* xv = (const float4*)x;
    float4* sAv = (float4*)sA;
    #pragma unroll
    for (int i = 0; i < 16; i++) {
        int v = tid + 128 * i;                // 0..2047
        int r = v >> 5, c = v & 31;
        int n = n0 + r;
        sAv[v] = (n < N_NODES) ? xv[(size_t)n * 32 + c]
                               : make_float4(0.f, 0.f, 0.f, 0.f);
    }
    __syncthreads();

    int tx = tid & 15;                        // j = tx + 16*jj
    int mg = tid >> 4;                        // 0..7 -> rows mg*8..mg*8+7
    float acc[8][4] = {};

    #pragma unroll 2
    for (int k4 = 0; k4 < D_IN / 4; k4++) {
        float4 a[8];
        #pragma unroll
        for (int m = 0; m < 8; m++)
            a[m] = ((const float4*)&sA[(mg * 8 + m) * D_IN])[k4];
        #pragma unroll
        for (int kk = 0; kk < 4; kk++) {
            int k = k4 * 4 + kk;
            float w[4];
            #pragma unroll
            for (int jj = 0; jj < 4; jj++) w[jj] = sW[k * D_H + tx + 16 * jj];
            #pragma unroll
            for (int m = 0; m < 8; m++) {
                float av = ((const float*)&a[m])[kk];
                #pragma unroll
                for (int jj = 0; jj < 4; jj++) acc[m][jj] += av * w[jj];
            }
        }
    }

    #pragma unroll
    for (int m = 0; m < 8; m++) {
        int n = n0 + mg * 8 + m;
        if (n < N_NODES) {
            #pragma unroll
            for (int jj = 0; jj < 4; jj++)
                g_g1[(size_t)n * D_H + tx + 16 * jj] = acc[m][jj];
        }
    }
}

// ---------------- scale: g1[n,:] *= dinv[n] (after join) ----------------
__global__ __launch_bounds__(256) void scale1_kernel() {
    int i = blockIdx.x * blockDim.x + threadIdx.x;   // float4 index
    if (i >= N_NODES * 16) return;
    float di = g_dinv[i >> 4];
    float4* p = (float4*)g_g1 + i;
    float4 v = *p;
    *p = make_float4(v.x * di, v.y * di, v.z * di, v.w * di);
}

// ---------------- Gather 1 + relu + dropout (fused) ----------------
// 16 lanes per node; lane owns one float4 column of the 64-float row.
__global__ __launch_bounds__(256) void gather1_kernel(const float* __restrict__ b1) {
    int tid  = threadIdx.x;
    int lane = tid & 15;
    int node = blockIdx.x * 16 + (tid >> 4);

    const float4* g1v = (const float4*)g_g1;
    size_t rl = (size_t)node * 16 + lane;
    float4 acc0 = g1v[rl];                       // self-loop term (pre-scaled)
    float4 acc1 = make_float4(0.f, 0.f, 0.f, 0.f);

    int deg = g_wp[node];
    const int* cp = g_col + node * CAP;

    int j = 0;
    for (; j + 4 <= deg; j += 4) {
        int4 s4 = *(const int4*)(cp + j);
        float4 v0 = g1v[(size_t)s4.x * 16 + lane];
        float4 v1 = g1v[(size_t)s4.y * 16 + lane];
        float4 v2 = g1v[(size_t)s4.z * 16 + lane];
        float4 v3 = g1v[(size_t)s4.w * 16 + lane];
        acc0 = f4add(acc0, f4add(v0, v1));
        acc1 = f4add(acc1, f4add(v2, v3));
    }
    for (; j < deg; j++) {
        int s = cp[j];
        acc0 = f4add(acc0, g1v[(size_t)s * 16 + lane]);
    }
    float4 acc = f4add(acc0, acc1);

    float di = g_dinv[node];
    float4 bb = ((const float4*)b1)[lane];
    float v[4] = { fmaxf(acc.x * di + bb.x, 0.f),
                   fmaxf(acc.y * di + bb.y, 0.f),
                   fmaxf(acc.z * di + bb.z, 0.f),
                   fmaxf(acc.w * di + bb.w, 0.f) };

    // Partitionable threefry: bits = o0 ^ o1 of threefry(key, 0, elem_idx)
    uint32_t gidx = (uint32_t)(node * D_H + lane * 4);
    float4 outv;
    #pragma unroll
    for (int k = 0; k < 4; k++) {
        uint32_t o0, o1;
        threefry2x32(0u, 42u, 0u, gidx + k, o0, o1);
        uint32_t bits = o0 ^ o1;
        float u = __uint_as_float((bits >> 9) | 0x3f800000u) - 1.0f;
        ((float*)&outv)[k] = (u < 0.8f) ? v[k] * 1.25f : 0.f;
    }
    ((float4*)g_h1d)[rl] = outv;
}

// ---------------- GEMM 2: g2[n,:] = (h1d[n,:] @ W2) * dinv[n] ----------------
__global__ __launch_bounds__(256) void gemm2_kernel(const float* __restrict__ W2) {
    __shared__ float sW[D_H * D_OUT];         // 8 KB, [k][j]
    __shared__ float sA[64 * D_H];            // 16 KB, [m][k]
    int tid = threadIdx.x;
    int n0  = blockIdx.x * 64;

    #pragma unroll
    for (int i = 0; i < 2; i++)
        ((float4*)sW)[tid + 256 * i] = ((const float4*)W2)[tid + 256 * i];

    const float4* hv = (const float4*)g_h1d;
    float4* sAv = (float4*)sA;
    #pragma unroll
    for (int i = 0; i < 4; i++) {
        int v = tid + 256 * i;
        int r = v >> 4, c = v & 15;
        int n = n0 + r;
        sAv[v] = (n < N_NODES) ? hv[(size_t)n * 16 + c]
                               : make_float4(0.f, 0.f, 0.f, 0.f);
    }
    __syncthreads();

    int tx = tid & 15;
    int mg = tid >> 4;
    float acc[4][2] = {};

    #pragma unroll 4
    for (int k4 = 0; k4 < D_H / 4; k4++) {
        float4 a[4];
        #pragma unroll
        for (int m = 0; m < 4; m++)
            a[m] = ((const float4*)&sA[(mg * 4 + m) * D_H])[k4];
        #pragma unroll
        for (int kk = 0; kk < 4; kk++) {
            int k = k4 * 4 + kk;
            float w0 = sW[k * D_OUT + tx];
            float w1 = sW[k * D_OUT + tx + 16];
            #pragma unroll
            for (int m = 0; m < 4; m++) {
                float av = ((const float*)&a[m])[kk];
                acc[m][0] += av * w0;
                acc[m][1] += av * w1;
            }
        }
    }

    #pragma unroll
    for (int m = 0; m < 4; m++) {
        int n = n0 + mg * 4 + m;
        if (n < N_NODES) {
            float di = g_dinv[n];
            g_g2[(size_t)n * D_OUT + tx]      = acc[m][0] * di;
            g_g2[(size_t)n * D_OUT + tx + 16] = acc[m][1] * di;
        }
    }
}

// ---------------- Gather 2 + bias (fused final) ----------------
__global__ __launch_bounds__(256) void gather2_kernel(const float* __restrict__ b2,
                                                      float* __restrict__ out) {
    int tid  = threadIdx.x;
    int lane = tid & 7;
    int node = blockIdx.x * 32 + (tid >> 3);

    const float4* g2v = (const float4*)g_g2;
    size_t rl = (size_t)node * 8 + lane;
    float4 acc0 = g2v[rl];                       // self-loop
    float4 acc1 = make_float4(0.f, 0.f, 0.f, 0.f);

    int deg = g_wp[node];
    const int* cp = g_col + node * CAP;

    int j = 0;
    for (; j + 4 <= deg; j += 4) {
        int4 s4 = *(const int4*)(cp + j);
        float4 v0 = g2v[(size_t)s4.x * 8 + lane];
        float4 v1 = g2v[(size_t)s4.y * 8 + lane];
        float4 v2 = g2v[(size_t)s4.z * 8 + lane];
        float4 v3 = g2v[(size_t)s4.w * 8 + lane];
        acc0 = f4add(acc0, f4add(v0, v1));
        acc1 = f4add(acc1, f4add(v2, v3));
    }
    for (; j < deg; j++) {
        int s = cp[j];
        acc0 = f4add(acc0, g2v[(size_t)s * 8 + lane]);
    }
    float4 acc = f4add(acc0, acc1);

    float di = g_dinv[node];
    float4 bb = ((const float4*)b2)[lane];
    float4 o = make_float4(acc.x * di + bb.x, acc.y * di + bb.y,
                           acc.z * di + bb.z, acc.w * di + bb.w);
    ((float4*)out)[rl] = o;
}

// ---------------- forked-capture plumbing (host objects, created once) ----------------
static cudaStream_t g_side = nullptr;
static cudaEvent_t  g_evA  = nullptr;
static cudaEvent_t  g_evB  = nullptr;
struct SideInit {
    SideInit() {
        cudaStreamCreateWithFlags(&g_side, cudaStreamNonBlocking);
        cudaEventCreateWithFlags(&g_evA, cudaEventDisableTiming);
        cudaEventCreateWithFlags(&g_evB, cudaEventDisableTiming);
    }
};
static SideInit g_side_init;

// ---------------- launch ----------------
extern "C" void kernel_launch(void* const* d_in, const int* in_sizes, int n_in,
                              void* d_out, int out_size) {
    const float* x  = (const float*)d_in[0];
    const int*   ei = (const int*)d_in[1];     // int32 (JAX x64 disabled)
    const float* W1 = (const float*)d_in[2];
    const float* b1 = (const float*)d_in[3];
    const float* W2 = (const float*)d_in[4];
    const float* b2 = (const float*)d_in[5];
    float* out = (float*)d_out;
    const int E = in_sizes[1] / 2;

    const int T = 256;

    // fork: CSR build on side stream, concurrent with gemm1 on main stream
    cudaEventRecord(g_evA, 0);
    cudaStreamWaitEvent(g_side, g_evA, 0);
    zero_kernel<<<(N_NODES + T - 1) / T, T, 0, g_side>>>();
    fill_kernel<<<(E + T - 1) / T, T, 0, g_side>>>(ei, E);
    dinv_kernel<<<(N_NODES + T - 1) / T, T, 0, g_side>>>();
    cudaEventRecord(g_evB, g_side);

    gemm1_kernel<<<(N_NODES + 63) / 64, 128>>>(x, W1);   // main stream

    cudaStreamWaitEvent(0, g_evB, 0);                    // join
    scale1_kernel<<<(N_NODES * 16 + T - 1) / T, T>>>();
    gather1_kernel<<<(N_NODES + 15) / 16, T>>>(b1);
    gemm2_kernel<<<(N_NODES + 63) / 64, T>>>(W2);
    gather2_kernel<<<(N_NODES + 31) / 32, T>>>(b2, out);
}

// round 16
// speedup vs baseline: 1.2647x; 1.1172x over previous
#include <cuda_runtime.h>
#include <stdint.h>

#define N_NODES 100000
#define D_IN    128
#define D_H     64
#define D_OUT   32
#define CAP     64          // max in-degree slots (multinomial mean 16, max ~35)
#define SWK     132         // padded smem stride (conflict-free mma frag loads)

// ---------------- scratch (static device globals; no allocation) ----------------
__device__ int   g_wp  [N_NODES];                        // fill cursor == in-degree
__device__ float g_dinv[N_NODES];
__device__ __align__(16) int   g_col[N_NODES * CAP];     // src lists per dst
__device__ __align__(16) float g_g1 [N_NODES * D_H];     // (x@W1) * dinv[n]
__device__ __align__(16) float g_h1d[N_NODES * D_H];     // relu+dropout result
__device__ __align__(16) float g_g2 [N_NODES * D_OUT];   // (h1d@W2) * dinv[n]

__device__ __forceinline__ float4 f4add(float4 a, float4 b) {
    return make_float4(a.x + b.x, a.y + b.y, a.z + b.z, a.w + b.w);
}

__device__ __forceinline__ uint32_t cvt_tf32(float f) {
    uint32_t u; asm("cvt.rna.tf32.f32 %0, %1;" : "=r"(u) : "f"(f)); return u;
}

__device__ __forceinline__ void mma_tf32(float c[4], uint32_t a0, uint32_t a1,
                                         uint32_t a2, uint32_t a3,
                                         uint32_t b0, uint32_t b1) {
    asm volatile("mma.sync.aligned.m16n8k8.row.col.f32.tf32.tf32.f32 "
                 "{%0,%1,%2,%3}, {%4,%5,%6,%7}, {%8,%9}, {%0,%1,%2,%3};"
                 : "+f"(c[0]), "+f"(c[1]), "+f"(c[2]), "+f"(c[3])
                 : "r"(a0), "r"(a1), "r"(a2), "r"(a3), "r"(b0), "r"(b1));
}

// Exact JAX threefry2x32 (20 rounds), key = (k0, k1)
__device__ __forceinline__ void threefry2x32(uint32_t k0, uint32_t k1,
                                             uint32_t x0, uint32_t x1,
                                             uint32_t& o0, uint32_t& o1) {
    uint32_t ks2 = k0 ^ k1 ^ 0x1BD11BDAu;
    x0 += k0; x1 += k1;
#define TFR(r) { x0 += x1; x1 = (x1 << r) | (x1 >> (32 - r)); x1 ^= x0; }
    TFR(13) TFR(15) TFR(26) TFR(6)
    x0 += k1;  x1 += ks2 + 1u;
    TFR(17) TFR(29) TFR(16) TFR(24)
    x0 += ks2; x1 += k0 + 2u;
    TFR(13) TFR(15) TFR(26) TFR(6)
    x0 += k0;  x1 += k1 + 3u;
    TFR(17) TFR(29) TFR(16) TFR(24)
    x0 += k1;  x1 += ks2 + 4u;
    TFR(13) TFR(15) TFR(26) TFR(6)
    x0 += ks2; x1 += k0 + 5u;
#undef TFR
    o0 = x0; o1 = x1;
}

// ---------------- CSR-lite build ----------------
__global__ void zero_kernel() {
    int i = blockIdx.x * blockDim.x + threadIdx.x;
    if (i < N_NODES) g_wp[i] = 0;
}

__global__ void fill_kernel(const int* __restrict__ ei, int E) {
    int e = blockIdx.x * blockDim.x + threadIdx.x;
    if (e >= E) return;
    int d = ei[E + e];
    int p = atomicAdd(&g_wp[d], 1);
    if (p < CAP) g_col[d * CAP + p] = ei[e];
}

__global__ void dinv_kernel() {
    int i = blockIdx.x * blockDim.x + threadIdx.x;
    if (i < N_NODES) g_dinv[i] = rsqrtf((float)(g_wp[i] + 1));  // +1 self-loop
}

// ---------------- GEMM 1 (tf32 tensor cores) ----------------
// g1[n,:] = (x[n,:] @ W1) * dinv[n].
// Block: 64 nodes x 64 feats x K=128, 256 threads (8 warps).
// Computes D^T: MMA M-dim = features (A = W^T), MMA N-dim = nodes (B = x^T).
// Warp w: feature base (w%4)*16, node base (w/4)*32 -> 4 m8 node tiles.
__global__ __launch_bounds__(256) void gemm1_kernel(const float* __restrict__ x,
                                                    const float* __restrict__ W1) {
    __shared__ uint32_t sWt[D_H * SWK];       // W^T tf32 bits, [n_feat][k]
    __shared__ uint32_t sA [64 * SWK];        // x tf32 bits, [node][k]
    __shared__ float sDinv[64];
    int tid = threadIdx.x;
    int n0  = blockIdx.x * 64;

    if (tid < 64) {
        int n = n0 + tid;
        sDinv[tid] = (n < N_NODES) ? g_dinv[n] : 0.f;
    }

    // x tile (64 x 128) -> tf32
    const float4* xv = (const float4*)x;
    #pragma unroll
    for (int i = 0; i < 8; i++) {
        int v = tid + 256 * i;                // 0..2047 float4
        int r = v >> 5, c = v & 31;
        int n = n0 + r;
        float4 val = (n < N_NODES) ? xv[(size_t)n * 32 + c]
                                   : make_float4(0.f, 0.f, 0.f, 0.f);
        uint32_t* dst = &sA[r * SWK + c * 4];
        dst[0] = cvt_tf32(val.x); dst[1] = cvt_tf32(val.y);
        dst[2] = cvt_tf32(val.z); dst[3] = cvt_tf32(val.w);
    }
    // W^T (transpose 128x64 -> [feat][k]) -> tf32
    const float4* Wv = (const float4*)W1;
    #pragma unroll
    for (int i = 0; i < 8; i++) {
        int v = tid + 256 * i;                // 0..2047 float4 of W1
        int k = v >> 4, nq = v & 15;
        float4 w = Wv[v];
        sWt[(nq * 4 + 0) * SWK + k] = cvt_tf32(w.x);
        sWt[(nq * 4 + 1) * SWK + k] = cvt_tf32(w.y);
        sWt[(nq * 4 + 2) * SWK + k] = cvt_tf32(w.z);
        sWt[(nq * 4 + 3) * SWK + k] = cvt_tf32(w.w);
    }
    __syncthreads();

    int w    = tid >> 5;
    int lane = tid & 31;
    int g    = lane >> 2, tig = lane & 3;
    int nb   = (w & 3) * 16;                  // feature base
    int mb   = (w >> 2) * 32;                 // node base (within block)

    float c[4][4] = {};

    #pragma unroll
    for (int k8 = 0; k8 < 16; k8++) {
        int k = k8 * 8;
        uint32_t a0 = sWt[(nb + g) * SWK + k + tig];
        uint32_t a1 = sWt[(nb + g + 8) * SWK + k + tig];
        uint32_t a2 = sWt[(nb + g) * SWK + k + tig + 4];
        uint32_t a3 = sWt[(nb + g + 8) * SWK + k + tig + 4];
        #pragma unroll
        for (int mt = 0; mt < 4; mt++) {
            int m0 = mb + mt * 8;
            uint32_t b0 = sA[(m0 + g) * SWK + k + tig];
            uint32_t b1 = sA[(m0 + g) * SWK + k + tig + 4];
            mma_tf32(c[mt], a0, a1, a2, a3, b0, b1);
        }
    }

    #pragma unroll
    for (int mt = 0; mt < 4; mt++) {
        int m0 = mb + mt * 8;
        int mA = m0 + 2 * tig;
        int mB = mA + 1;
        int gA = n0 + mA, gB = n0 + mB;
        float dA = sDinv[mA], dB = sDinv[mB];
        if (gA < N_NODES) {
            g_g1[(size_t)gA * D_H + nb + g]     = c[mt][0] * dA;
            g_g1[(size_t)gA * D_H + nb + g + 8] = c[mt][2] * dA;
        }
        if (gB < N_NODES) {
            g_g1[(size_t)gB * D_H + nb + g]     = c[mt][1] * dB;
            g_g1[(size_t)gB * D_H + nb + g + 8] = c[mt][3] * dB;
        }
    }
}

// ---------------- Gather 1 + relu + dropout (fused) ----------------
// 16 lanes per node; lane owns one float4 column of the 64-float row.
__global__ __launch_bounds__(256) void gather1_kernel(const float* __restrict__ b1) {
    int tid  = threadIdx.x;
    int lane = tid & 15;
    int node = blockIdx.x * 16 + (tid >> 4);

    const float4* g1v = (const float4*)g_g1;
    size_t rl = (size_t)node * 16 + lane;
    float4 acc0 = g1v[rl];                       // self-loop term (pre-scaled)
    float4 acc1 = make_float4(0.f, 0.f, 0.f, 0.f);

    int deg = g_wp[node];
    const int* cp = g_col + node * CAP;

    int j = 0;
    for (; j + 4 <= deg; j += 4) {
        int4 s4 = *(const int4*)(cp + j);
        float4 v0 = g1v[(size_t)s4.x * 16 + lane];
        float4 v1 = g1v[(size_t)s4.y * 16 + lane];
        float4 v2 = g1v[(size_t)s4.z * 16 + lane];
        float4 v3 = g1v[(size_t)s4.w * 16 + lane];
        acc0 = f4add(acc0, f4add(v0, v1));
        acc1 = f4add(acc1, f4add(v2, v3));
    }
    for (; j < deg; j++) {
        int s = cp[j];
        acc0 = f4add(acc0, g1v[(size_t)s * 16 + lane]);
    }
    float4 acc = f4add(acc0, acc1);

    float di = g_dinv[node];
    float4 bb = ((const float4*)b1)[lane];
    float v[4] = { fmaxf(acc.x * di + bb.x, 0.f),
                   fmaxf(acc.y * di + bb.y, 0.f),
                   fmaxf(acc.z * di + bb.z, 0.f),
                   fmaxf(acc.w * di + bb.w, 0.f) };

    // Partitionable threefry: bits = o0 ^ o1 of threefry(key, 0, elem_idx)
    uint32_t gidx = (uint32_t)(node * D_H + lane * 4);
    float4 outv;
    #pragma unroll
    for (int k = 0; k < 4; k++) {
        uint32_t o0, o1;
        threefry2x32(0u, 42u, 0u, gidx + k, o0, o1);
        uint32_t bits = o0 ^ o1;
        float u = __uint_as_float((bits >> 9) | 0x3f800000u) - 1.0f;
        ((float*)&outv)[k] = (u < 0.8f) ? v[k] * 1.25f : 0.f;
    }
    ((float4*)g_h1d)[rl] = outv;
}

// ---------------- GEMM 2: g2[n,:] = (h1d[n,:] @ W2) * dinv[n] ----------------
__global__ __launch_bounds__(256) void gemm2_kernel(const float* __restrict__ W2) {
    __shared__ float sW[D_H * D_OUT];         // 8 KB, [k][j]
    __shared__ float sA[64 * D_H];            // 16 KB, [m][k]
    int tid = threadIdx.x;
    int n0  = blockIdx.x * 64;

    #pragma unroll
    for (int i = 0; i < 2; i++)
        ((float4*)sW)[tid + 256 * i] = ((const float4*)W2)[tid + 256 * i];

    const float4* hv = (const float4*)g_h1d;
    float4* sAv = (float4*)sA;
    #pragma unroll
    for (int i = 0; i < 4; i++) {
        int v = tid + 256 * i;
        int r = v >> 4, c = v & 15;
        int n = n0 + r;
        sAv[v] = (n < N_NODES) ? hv[(size_t)n * 16 + c]
                               : make_float4(0.f, 0.f, 0.f, 0.f);
    }
    __syncthreads();

    int tx = tid & 15;
    int mg = tid >> 4;
    float acc[4][2] = {};

    #pragma unroll 4
    for (int k4 = 0; k4 < D_H / 4; k4++) {
        float4 a[4];
        #pragma unroll
        for (int m = 0; m < 4; m++)
            a[m] = ((const float4*)&sA[(mg * 4 + m) * D_H])[k4];
        #pragma unroll
        for (int kk = 0; kk < 4; kk++) {
            int k = k4 * 4 + kk;
            float w0 = sW[k * D_OUT + tx];
            float w1 = sW[k * D_OUT + tx + 16];
            #pragma unroll
            for (int m = 0; m < 4; m++) {
                float av = ((const float*)&a[m])[kk];
                acc[m][0] += av * w0;
                acc[m][1] += av * w1;
            }
        }
    }

    #pragma unroll
    for (int m = 0; m < 4; m++) {
        int n = n0 + mg * 4 + m;
        if (n < N_NODES) {
            float di = g_dinv[n];
            g_g2[(size_t)n * D_OUT + tx]      = acc[m][0] * di;
            g_g2[(size_t)n * D_OUT + tx + 16] = acc[m][1] * di;
        }
    }
}

// ---------------- Gather 2 + bias (fused final) ----------------
__global__ __launch_bounds__(256) void gather2_kernel(const float* __restrict__ b2,
                                                      float* __restrict__ out) {
    int tid  = threadIdx.x;
    int lane = tid & 7;
    int node = blockIdx.x * 32 + (tid >> 3);

    const float4* g2v = (const float4*)g_g2;
    size_t rl = (size_t)node * 8 + lane;
    float4 acc0 = g2v[rl];                       // self-loop
    float4 acc1 = make_float4(0.f, 0.f, 0.f, 0.f);

    int deg = g_wp[node];
    const int* cp = g_col + node * CAP;

    int j = 0;
    for (; j + 4 <= deg; j += 4) {
        int4 s4 = *(const int4*)(cp + j);
        float4 v0 = g2v[(size_t)s4.x * 8 + lane];
        float4 v1 = g2v[(size_t)s4.y * 8 + lane];
        float4 v2 = g2v[(size_t)s4.z * 8 + lane];
        float4 v3 = g2v[(size_t)s4.w * 8 + lane];
        acc0 = f4add(acc0, f4add(v0, v1));
        acc1 = f4add(acc1, f4add(v2, v3));
    }
    for (; j < deg; j++) {
        int s = cp[j];
        acc0 = f4add(acc0, g2v[(size_t)s * 8 + lane]);
    }
    float4 acc = f4add(acc0, acc1);

    float di = g_dinv[node];
    float4 bb = ((const float4*)b2)[lane];
    float4 o = make_float4(acc.x * di + bb.x, acc.y * di + bb.y,
                           acc.z * di + bb.z, acc.w * di + bb.w);
    ((float4*)out)[rl] = o;
}

// ---------------- launch ----------------
extern "C" void kernel_launch(void* const* d_in, const int* in_sizes, int n_in,
                              void* d_out, int out_size) {
    const float* x  = (const float*)d_in[0];
    const int*   ei = (const int*)d_in[1];     // int32 (JAX x64 disabled)
    const float* W1 = (const float*)d_in[2];
    const float* b1 = (const float*)d_in[3];
    const float* W2 = (const float*)d_in[4];
    const float* b2 = (const float*)d_in[5];
    float* out = (float*)d_out;
    const int E = in_sizes[1] / 2;

    const int T = 256;
    zero_kernel<<<(N_NODES + T - 1) / T, T>>>();
    fill_kernel<<<(E + T - 1) / T, T>>>(ei, E);
    dinv_kernel<<<(N_NODES + T - 1) / T, T>>>();
    gemm1_kernel<<<(N_NODES + 63) / 64, T>>>(x, W1);
    gather1_kernel<<<(N_NODES + 15) / 16, T>>>(b1);
    gemm2_kernel<<<(N_NODES + 63) / 64, T>>>(W2);
    gather2_kernel<<<(N_NODES + 31) / 32, T>>>(b2, out);
}

// round 17
// speedup vs baseline: 1.3388x; 1.0586x over previous
#include <cuda_runtime.h>
#include <stdint.h>

#define N_NODES 100000
#define D_IN    128
#define D_H     64
#define D_OUT   32
#define CAP     64          // max in-degree slots (multinomial mean 16, max ~35)
#define SWK     132         // padded smem stride for x tile (conflict-free)
#define WTS     144         // padded row stride of permuted global W (uint32)

// ---------------- scratch (static device globals; no allocation) ----------------
__device__ int   g_wp  [N_NODES];                        // fill cursor (self-cleaning)
__device__ int   g_deg [N_NODES];                        // in-degree snapshot
__device__ float g_dinv[N_NODES];
__device__ __align__(16) uint32_t g_wt[D_H * WTS];       // W1^T tf32, fragment-permuted
__device__ __align__(16) int   g_col[N_NODES * CAP];     // src lists per dst
__device__ __align__(16) float g_g1 [N_NODES * D_H];     // (x@W1) * dinv[n]
__device__ __align__(16) float g_h1d[N_NODES * D_H];     // relu+dropout result
__device__ __align__(16) float g_g2 [N_NODES * D_OUT];   // (h1d@W2) * dinv[n]

__device__ __forceinline__ float4 f4add(float4 a, float4 b) {
    return make_float4(a.x + b.x, a.y + b.y, a.z + b.z, a.w + b.w);
}

__device__ __forceinline__ uint32_t cvt_tf32(float f) {
    uint32_t u; asm("cvt.rna.tf32.f32 %0, %1;" : "=r"(u) : "f"(f)); return u;
}

__device__ __forceinline__ void mma_tf32(float c[4], uint32_t a0, uint32_t a1,
                                         uint32_t a2, uint32_t a3,
                                         uint32_t b0, uint32_t b1) {
    asm volatile("mma.sync.aligned.m16n8k8.row.col.f32.tf32.tf32.f32 "
                 "{%0,%1,%2,%3}, {%4,%5,%6,%7}, {%8,%9}, {%0,%1,%2,%3};"
                 : "+f"(c[0]), "+f"(c[1]), "+f"(c[2]), "+f"(c[3])
                 : "r"(a0), "r"(a1), "r"(a2), "r"(a3), "r"(b0), "r"(b1));
}

// Exact JAX threefry2x32 (20 rounds), key = (k0, k1)
__device__ __forceinline__ void threefry2x32(uint32_t k0, uint32_t k1,
                                             uint32_t x0, uint32_t x1,
                                             uint32_t& o0, uint32_t& o1) {
    uint32_t ks2 = k0 ^ k1 ^ 0x1BD11BDAu;
    x0 += k0; x1 += k1;
#define TFR(r) { x0 += x1; x1 = (x1 << r) | (x1 >> (32 - r)); x1 ^= x0; }
    TFR(13) TFR(15) TFR(26) TFR(6)
    x0 += k1;  x1 += ks2 + 1u;
    TFR(17) TFR(29) TFR(16) TFR(24)
    x0 += ks2; x1 += k0 + 2u;
    TFR(13) TFR(15) TFR(26) TFR(6)
    x0 += k0;  x1 += k1 + 3u;
    TFR(17) TFR(29) TFR(16) TFR(24)
    x0 += k1;  x1 += ks2 + 4u;
    TFR(13) TFR(15) TFR(26) TFR(6)
    x0 += ks2; x1 += k0 + 5u;
#undef TFR
    o0 = x0; o1 = x1;
}

// ---------------- CSR-lite build ----------------
__global__ void fill_kernel(const int* __restrict__ ei, int E) {
    int e = blockIdx.x * blockDim.x + threadIdx.x;
    if (e >= E) return;
    int d = ei[E + e];
    int p = atomicAdd(&g_wp[d], 1);
    if (p < CAP) g_col[d * CAP + p] = ei[e];
}

// snapshot degree, compute dinv, and reset the cursor for the next replay
__global__ void dinv_kernel() {
    int i = blockIdx.x * blockDim.x + threadIdx.x;
    if (i < N_NODES) {
        int c = g_wp[i];
        g_deg[i]  = c;
        g_dinv[i] = rsqrtf((float)(c + 1));   // +1 self-loop
        g_wp[i]   = 0;
    }
}

// ---------------- W1^T -> tf32, fragment-permuted global (runs once/launch) ----------------
// Layout: g_wt[f * WTS + (k/16)*16 + (k%4)*4 + (k%16)/4]
// => uint4 at [f*WTS + chp*16 + tig*4] = {a0(k8a), a2(k8a), a0(k8b), a2(k8b)}
__global__ void wt_prep_kernel(const float* __restrict__ W1) {
    int idx = blockIdx.x * blockDim.x + threadIdx.x;   // 0..8191
    if (idx >= D_IN * D_H) return;
    int k = idx >> 6, f = idx & 63;
    int ch = k >> 4, cw = k & 15;
    int slot = (cw & 3) * 4 + (cw >> 2);
    g_wt[f * WTS + ch * 16 + slot] = cvt_tf32(W1[idx]);
}

// ---------------- GEMM 1 (tf32 tensor cores) ----------------
// g1[n,:] = (x[n,:] @ W1) * dinv[n].
// Block: 64 nodes x 64 feats x K=128, 256 threads (8 warps).
// A-fragments (W^T) from permuted global (L1-resident); B (x^T) from smem.
__global__ __launch_bounds__(256) void gemm1_kernel(const float* __restrict__ x) {
    __shared__ uint32_t sA[64 * SWK];         // x tf32 bits, [node][k]
    __shared__ float sDinv[64];
    int tid = threadIdx.x;
    int n0  = blockIdx.x * 64;

    if (tid < 64) {
        int n = n0 + tid;
        sDinv[tid] = (n < N_NODES) ? g_dinv[n] : 0.f;
    }

    // x tile (64 x 128) -> tf32, natural layout, vector-friendly stores
    const float4* xv = (const float4*)x;
    #pragma unroll
    for (int i = 0; i < 8; i++) {
        int v = tid + 256 * i;                // 0..2047 float4
        int r = v >> 5, c = v & 31;
        int n = n0 + r;
        float4 val = (n < N_NODES) ? xv[(size_t)n * 32 + c]
                                   : make_float4(0.f, 0.f, 0.f, 0.f);
        uint32_t* dst = &sA[r * SWK + c * 4];
        dst[0] = cvt_tf32(val.x); dst[1] = cvt_tf32(val.y);
        dst[2] = cvt_tf32(val.z); dst[3] = cvt_tf32(val.w);
    }
    __syncthreads();

    int w    = tid >> 5;
    int lane = tid & 31;
    int g    = lane >> 2, tig = lane & 3;
    int nb   = (w & 3) * 16;                  // feature base
    int mb   = (w >> 2) * 32;                 // node base (within block)

    float c[4][4] = {};
    const uint4* wtv = (const uint4*)g_wt;

    #pragma unroll
    for (int chp = 0; chp < 8; chp++) {       // 2 k8-steps per chunk
        uint4 aw0 = wtv[((nb + g)     * WTS + chp * 16 + tig * 4) >> 2];
        uint4 aw1 = wtv[((nb + g + 8) * WTS + chp * 16 + tig * 4) >> 2];
        int k = chp * 16;
        #pragma unroll
        for (int mt = 0; mt < 4; mt++) {
            int row = (mb + mt * 8 + g) * SWK + k + tig;
            uint32_t b0a = sA[row];
            uint32_t b1a = sA[row + 4];
            uint32_t b0b = sA[row + 8];
            uint32_t b1b = sA[row + 12];
            mma_tf32(c[mt], aw0.x, aw1.x, aw0.y, aw1.y, b0a, b1a);
            mma_tf32(c[mt], aw0.z, aw1.z, aw0.w, aw1.w, b0b, b1b);
        }
    }

    #pragma unroll
    for (int mt = 0; mt < 4; mt++) {
        int m0 = mb + mt * 8;
        int mA = m0 + 2 * tig;
        int mB = mA + 1;
        int gA = n0 + mA, gB = n0 + mB;
        float dA = sDinv[mA], dB = sDinv[mB];
        if (gA < N_NODES) {
            g_g1[(size_t)gA * D_H + nb + g]     = c[mt][0] * dA;
            g_g1[(size_t)gA * D_H + nb + g + 8] = c[mt][2] * dA;
        }
        if (gB < N_NODES) {
            g_g1[(size_t)gB * D_H + nb + g]     = c[mt][1] * dB;
            g_g1[(size_t)gB * D_H + nb + g + 8] = c[mt][3] * dB;
        }
    }
}

// ---------------- Gather 1 + relu + dropout (fused) ----------------
// 16 lanes per node; lane owns one float4 column of the 64-float row.
__global__ __launch_bounds__(256) void gather1_kernel(const float* __restrict__ b1) {
    int tid  = threadIdx.x;
    int lane = tid & 15;
    int node = blockIdx.x * 16 + (tid >> 4);

    const float4* g1v = (const float4*)g_g1;
    size_t rl = (size_t)node * 16 + lane;
    float4 acc0 = g1v[rl];                       // self-loop term (pre-scaled)
    float4 acc1 = make_float4(0.f, 0.f, 0.f, 0.f);

    int deg = g_deg[node];
    const int* cp = g_col + node * CAP;

    int j = 0;
    for (; j + 4 <= deg; j += 4) {
        int4 s4 = *(const int4*)(cp + j);
        float4 v0 = g1v[(size_t)s4.x * 16 + lane];
        float4 v1 = g1v[(size_t)s4.y * 16 + lane];
        float4 v2 = g1v[(size_t)s4.z * 16 + lane];
        float4 v3 = g1v[(size_t)s4.w * 16 + lane];
        acc0 = f4add(acc0, f4add(v0, v1));
        acc1 = f4add(acc1, f4add(v2, v3));
    }
    for (; j < deg; j++) {
        int s = cp[j];
        acc0 = f4add(acc0, g1v[(size_t)s * 16 + lane]);
    }
    float4 acc = f4add(acc0, acc1);

    float di = g_dinv[node];
    float4 bb = ((const float4*)b1)[lane];
    float v[4] = { fmaxf(acc.x * di + bb.x, 0.f),
                   fmaxf(acc.y * di + bb.y, 0.f),
                   fmaxf(acc.z * di + bb.z, 0.f),
                   fmaxf(acc.w * di + bb.w, 0.f) };

    // Partitionable threefry: bits = o0 ^ o1 of threefry(key, 0, elem_idx)
    uint32_t gidx = (uint32_t)(node * D_H + lane * 4);
    float4 outv;
    #pragma unroll
    for (int k = 0; k < 4; k++) {
        uint32_t o0, o1;
        threefry2x32(0u, 42u, 0u, gidx + k, o0, o1);
        uint32_t bits = o0 ^ o1;
        float u = __uint_as_float((bits >> 9) | 0x3f800000u) - 1.0f;
        ((float*)&outv)[k] = (u < 0.8f) ? v[k] * 1.25f : 0.f;
    }
    ((float4*)g_h1d)[rl] = outv;
}

// ---------------- GEMM 2: g2[n,:] = (h1d[n,:] @ W2) * dinv[n] ----------------
__global__ __launch_bounds__(256) void gemm2_kernel(const float* __restrict__ W2) {
    __shared__ float sW[D_H * D_OUT];         // 8 KB, [k][j]
    __shared__ float sA[64 * D_H];            // 16 KB, [m][k]
    int tid = threadIdx.x;
    int n0  = blockIdx.x * 64;

    #pragma unroll
    for (int i = 0; i < 2; i++)
        ((float4*)sW)[tid + 256 * i] = ((const float4*)W2)[tid + 256 * i];

    const float4* hv = (const float4*)g_h1d;
    float4* sAv = (float4*)sA;
    #pragma unroll
    for (int i = 0; i < 4; i++) {
        int v = tid + 256 * i;
        int r = v >> 4, c = v & 15;
        int n = n0 + r;
        sAv[v] = (n < N_NODES) ? hv[(size_t)n * 16 + c]
                               : make_float4(0.f, 0.f, 0.f, 0.f);
    }
    __syncthreads();

    int tx = tid & 15;
    int mg = tid >> 4;
    float acc[4][2] = {};

    #pragma unroll 4
    for (int k4 = 0; k4 < D_H / 4; k4++) {
        float4 a[4];
        #pragma unroll
        for (int m = 0; m < 4; m++)
            a[m] = ((const float4*)&sA[(mg * 4 + m) * D_H])[k4];
        #pragma unroll
        for (int kk = 0; kk < 4; kk++) {
            int k = k4 * 4 + kk;
            float w0 = sW[k * D_OUT + tx];
            float w1 = sW[k * D_OUT + tx + 16];
            #pragma unroll
            for (int m = 0; m < 4; m++) {
                float av = ((const float*)&a[m])[kk];
                acc[m][0] += av * w0;
                acc[m][1] += av * w1;
            }
        }
    }

    #pragma unroll
    for (int m = 0; m < 4; m++) {
        int n = n0 + mg * 4 + m;
        if (n < N_NODES) {
            float di = g_dinv[n];
            g_g2[(size_t)n * D_OUT + tx]      = acc[m][0] * di;
            g_g2[(size_t)n * D_OUT + tx + 16] = acc[m][1] * di;
        }
    }
}

// ---------------- Gather 2 + bias (fused final) ----------------
__global__ __launch_bounds__(256) void gather2_kernel(const float* __restrict__ b2,
                                                      float* __restrict__ out) {
    int tid  = threadIdx.x;
    int lane = tid & 7;
    int node = blockIdx.x * 32 + (tid >> 3);

    const float4* g2v = (const float4*)g_g2;
    size_t rl = (size_t)node * 8 + lane;
    float4 acc0 = g2v[rl];                       // self-loop
    float4 acc1 = make_float4(0.f, 0.f, 0.f, 0.f);

    int deg = g_deg[node];
    const int* cp = g_col + node * CAP;

    int j = 0;
    for (; j + 4 <= deg; j += 4) {
        int4 s4 = *(const int4*)(cp + j);
        float4 v0 = g2v[(size_t)s4.x * 8 + lane];
        float4 v1 = g2v[(size_t)s4.y * 8 + lane];
        float4 v2 = g2v[(size_t)s4.z * 8 + lane];
        float4 v3 = g2v[(size_t)s4.w * 8 + lane];
        acc0 = f4add(acc0, f4add(v0, v1));
        acc1 = f4add(acc1, f4add(v2, v3));
    }
    for (; j < deg; j++) {
        int s = cp[j];
        acc0 = f4add(acc0, g2v[(size_t)s * 8 + lane]);
    }
    float4 acc = f4add(acc0, acc1);

    float di = g_dinv[node];
    float4 bb = ((const float4*)b2)[lane];
    float4 o = make_float4(acc.x * di + bb.x, acc.y * di + bb.y,
                           acc.z * di + bb.z, acc.w * di + bb.w);
    ((float4*)out)[rl] = o;
}

// ---------------- launch ----------------
extern "C" void kernel_launch(void* const* d_in, const int* in_sizes, int n_in,
                              void* d_out, int out_size) {
    const float* x  = (const float*)d_in[0];
    const int*   ei = (const int*)d_in[1];     // int32 (JAX x64 disabled)
    const float* W1 = (const float*)d_in[2];
    const float* b1 = (const float*)d_in[3];
    const float* W2 = (const float*)d_in[4];
    const float* b2 = (const float*)d_in[5];
    float* out = (float*)d_out;
    const int E = in_sizes[1] / 2;

    const int T = 256;
    wt_prep_kernel<<<(D_IN * D_H + T - 1) / T, T>>>(W1);
    fill_kernel<<<(E + T - 1) / T, T>>>(ei, E);
    dinv_kernel<<<(N_NODES + T - 1) / T, T>>>();
    gemm1_kernel<<<(N_NODES + 63) / 64, T>>>(x);
    gather1_kernel<<<(N_NODES + 15) / 16, T>>>(b1);
    gemm2_kernel<<<(N_NODES + 63) / 64, T>>>(W2);
    gather2_kernel<<<(N_NODES + 31) / 32, T>>>(b2, out);
}